// round 3
// baseline (speedup 1.0000x reference)
#include <cuda_runtime.h>
#include <stdint.h>

// Shapes (fixed by the problem)
#define B   8
#define C   256
#define HIN 64          // input spatial 64x64
#define S   (HIN*HIN)   // 4096
#define HO  256         // output spatial 256x256
#define K   21
#define EPSF 1e-6f

// ---------------- scratch (__device__ globals; no allocations) ----------------
__device__ uint64_t g_T[B * HIN * HO * 3];       // [b][r][X] x 3 u64 (8-bit class fields, 1/8 units)
__device__ float    g_W[B * K * S];              // [b][k][s] weights (true value, multiples of 1/64)
__device__ float    g_counts[B * K];             // exact pixel counts per (b,k)
__device__ float    g_sums[B * K * C];           // per-image per-class feature sums

// bilinear gather weight (in 1/8 units) of input index r from output index Yx
__device__ __forceinline__ int bil_w8(int Yx, int r) {
    int t  = 2 * Yx - 3;            // 8*iy
    int y0 = ((t + 8) >> 3) - 1;    // floor(iy), t >= -3
    int f8 = (t + 8) & 7;           // 8*frac
    int y0c = min(max(y0, 0), HIN - 1);
    int y1c = min(max(y0 + 1, 0), HIN - 1);
    int w = 0;
    if (y0c == r) w += 8 - f8;
    if (y1c == r) w += f8;
    return w;
}

// ---------------- Kernel A: row-downsample one-hot masks (integer, packed) ----
// grid (HIN, B), block 256 (threads = output column X)
__global__ void kernA(const int* __restrict__ masks) {
    int r = blockIdx.x;     // input row 0..63
    int b = blockIdx.y;
    int X = threadIdx.x;    // output col 0..255

    uint64_t a0 = 0, a1 = 0, a2 = 0;
    #pragma unroll
    for (int dy = 0; dy < 8; dy++) {
        int Y = 4 * r - 2 + dy;
        if (Y < 0 || Y >= HO) continue;
        int w = bil_w8(Y, r);
        if (w == 0) continue;
        int lbl = masks[(b * HO + Y) * HO + X];
        if ((unsigned)lbl < (unsigned)K) {
            uint64_t add = (uint64_t)w << ((lbl & 7) * 8);
            int sel = lbl >> 3;
            if (sel == 0)      a0 += add;
            else if (sel == 1) a1 += add;
            else               a2 += add;
        }
    }
    uint64_t* Tp = &g_T[(((size_t)b * HIN + r) * HO + X) * 3];
    Tp[0] = a0; Tp[1] = a1; Tp[2] = a2;
}

// ---------------- Kernel B: col-downsample T -> W (float) ---------------------
// grid 128, block 256 ; thread -> (b, y, x)
__global__ void kernB() {
    int g = blockIdx.x * blockDim.x + threadIdx.x;   // 0 .. 32767
    int b = g >> 12;
    int y = (g >> 6) & 63;
    int x = g & 63;

    unsigned acc[K];
    #pragma unroll
    for (int k = 0; k < K; k++) acc[k] = 0u;

    #pragma unroll
    for (int dx = 0; dx < 8; dx++) {
        int X = 4 * x - 2 + dx;
        if (X < 0 || X >= HO) continue;
        int w = bil_w8(X, x);
        if (w == 0) continue;
        const uint64_t* Tp = &g_T[(((size_t)b * HIN + y) * HO + X) * 3];
        uint64_t a0 = Tp[0], a1 = Tp[1], a2 = Tp[2];
        #pragma unroll
        for (int j = 0; j < 8; j++) acc[j]      += (unsigned)w * (unsigned)((a0 >> (8 * j)) & 0xFFull);
        #pragma unroll
        for (int j = 0; j < 8; j++) acc[8 + j]  += (unsigned)w * (unsigned)((a1 >> (8 * j)) & 0xFFull);
        #pragma unroll
        for (int j = 0; j < 5; j++) acc[16 + j] += (unsigned)w * (unsigned)((a2 >> (8 * j)) & 0xFFull);
    }
    int s = y * HIN + x;
    float* Wb = &g_W[(size_t)b * K * S];
    #pragma unroll
    for (int k = 0; k < K; k++)
        Wb[k * S + s] = (float)acc[k] * (1.0f / 64.0f);   // coalesced per-k (consecutive threads -> consecutive s)
}

// ---------------- Kernel C: counts[b,k] = sum_s W[b,k,s] (exact) -------------
// grid B*K, block 256
__global__ void kernC() {
    int bk = blockIdx.x;
    const float* Wp = &g_W[(size_t)bk * S];
    float v = 0.f;
    for (int i = threadIdx.x; i < S; i += 256) v += Wp[i];
    __shared__ float red[256];
    red[threadIdx.x] = v;
    __syncthreads();
    for (int o = 128; o > 0; o >>= 1) {
        if (threadIdx.x < o) red[threadIdx.x] += red[threadIdx.x + o];
        __syncthreads();
    }
    if (threadIdx.x == 0) g_counts[bk] = red[0];
}

// ---------------- Kernel D: sums[b,k,c] = sum_s feats[b,c,s] * W[b,k,s] ------
// grid (32, B), block 256 = 8 warps (1 warp per channel), s chunked through smem
#define SCH 512
__global__ __launch_bounds__(256) void kernD(const float* __restrict__ feats) {
    int b    = blockIdx.y;
    int warp = threadIdx.x >> 5;
    int lane = threadIdx.x & 31;
    int c    = blockIdx.x * 8 + warp;

    __shared__ float4 Ws4[K * (SCH / 4)];   // 21*128 float4 = 43008 B

    float acc[K];
    #pragma unroll
    for (int k = 0; k < K; k++) acc[k] = 0.f;

    const float4* f4 = (const float4*)(feats + ((size_t)b * C + c) * S);
    const float4* Wg = (const float4*)(&g_W[(size_t)b * K * S]);

    for (int chunk = 0; chunk < S / SCH; chunk++) {
        int s4base = chunk * (SCH / 4);
        __syncthreads();
        // cooperative load of W chunk: 21 * 128 float4
        for (int i = threadIdx.x; i < K * (SCH / 4); i += 256) {
            int k = i / (SCH / 4);
            int j = i - k * (SCH / 4);
            Ws4[i] = Wg[k * (S / 4) + s4base + j];
        }
        __syncthreads();
        #pragma unroll
        for (int i = 0; i < (SCH / 4) / 32; i++) {
            int sl = i * 32 + lane;
            float4 f = f4[s4base + sl];
            #pragma unroll
            for (int k = 0; k < K; k++) {
                float4 w = Ws4[k * (SCH / 4) + sl];
                acc[k] += f.x * w.x;
                acc[k] += f.y * w.y;
                acc[k] += f.z * w.z;
                acc[k] += f.w * w.w;
            }
        }
    }
    // warp-reduce each class
    #pragma unroll
    for (int k = 0; k < K; k++) {
        float v = acc[k];
        #pragma unroll
        for (int o = 16; o > 0; o >>= 1) v += __shfl_xor_sync(0xFFFFFFFFu, v, o);
        if (lane == 0) g_sums[((size_t)b * K + k) * C + c] = v;
    }
}

// ---------------- Kernel E: finalize prototypes ------------------------------
// grid K, block 256
__global__ void kernE(float* __restrict__ out) {
    int k = blockIdx.x;
    int c = threadIdx.x;
    __shared__ float inv[B];
    if (c < B) inv[c] = 1.0f / (g_counts[c * K + k] + EPSF);
    __syncthreads();
    float v = 0.f;
    #pragma unroll
    for (int b = 0; b < B; b++)
        v += g_sums[((size_t)b * K + k) * C + c] * inv[b];
    out[k * C + c] = v * (1.0f / (float)B);
}

// ---------------- launch -----------------------------------------------------
extern "C" void kernel_launch(void* const* d_in, const int* in_sizes, int n_in,
                              void* d_out, int out_size) {
    const float* feats = (const float*)d_in[0];   // [8,256,64,64]
    const int*   masks = (const int*)d_in[1];     // [8,256,256]
    float*       out   = (float*)d_out;           // [21,256]

    kernA<<<dim3(HIN, B), 256>>>(masks);
    kernB<<<128, 256>>>();
    kernC<<<B * K, 256>>>();
    kernD<<<dim3(C / 8, B), 256>>>(feats);
    kernE<<<K, 256>>>(out);
}

// round 4
// speedup vs baseline: 1.1882x; 1.1882x over previous
#include <cuda_runtime.h>
#include <stdint.h>

// Shapes (fixed by the problem)
#define B    8
#define C    256
#define HIN  64          // input spatial 64x64
#define S    (HIN*HIN)   // 4096
#define HO   256         // output spatial 256x256
#define K    21
#define EPSF 1e-6f
#define SPLIT 4          // s-range splits for kernD parallelism
#define SCH  512         // s-chunk staged in smem

// ---------------- scratch (__device__ globals; no allocations) ----------------
__device__ uint64_t g_T[B * HIN * HO * 3];        // [b][r][X] x3 u64 (8-bit class fields, 1/8 units)
__device__ float    g_W[B * K * S];               // [b][k][s] weights (multiples of 1/64)
__device__ unsigned g_icounts[B * K];             // 64 * pixel count (exact integer)
__device__ float    g_sums[SPLIT * B * K * C];    // partial per-image per-class feature sums

// bilinear gather weight (in 1/8 units) of input index r from output index Yx
__device__ __forceinline__ int bil_w8(int Yx, int r) {
    int t  = 2 * Yx - 3;            // 8*iy
    int y0 = ((t + 8) >> 3) - 1;    // floor(iy)
    int f8 = (t + 8) & 7;           // 8*frac
    int y0c = min(max(y0, 0), HIN - 1);
    int y1c = min(max(y0 + 1, 0), HIN - 1);
    int w = 0;
    if (y0c == r) w += 8 - f8;
    if (y1c == r) w += f8;
    return w;
}

// packed f32x2 helpers (sm_103a FFMA2 — ptxas will not auto-fuse from C++)
__device__ __forceinline__ void fma2(uint64_t& d, uint64_t a, uint64_t b) {
    asm("fma.rn.f32x2 %0, %1, %2, %0;" : "+l"(d) : "l"(a), "l"(b));
}
__device__ __forceinline__ uint64_t pack2(float x, float y) {
    uint64_t r; asm("mov.b64 %0, {%1, %2};" : "=l"(r) : "f"(x), "f"(y)); return r;
}
__device__ __forceinline__ void unpack2(float& x, float& y, uint64_t a) {
    asm("mov.b64 {%0, %1}, %2;" : "=f"(x), "=f"(y) : "l"(a));
}

// ---------------- Kernel A: row-downsample one-hot masks (integer, packed) ----
// grid (HIN, B), block 256 (threads = output column X); also zeroes g_icounts
__global__ void kernA(const int* __restrict__ masks) {
    int r = blockIdx.x;
    int b = blockIdx.y;
    int X = threadIdx.x;
    if (r == 0 && b == 0 && X < B * K) g_icounts[X] = 0u;

    uint64_t a0 = 0, a1 = 0, a2 = 0;
    #pragma unroll
    for (int dy = 0; dy < 8; dy++) {
        int Y = 4 * r - 2 + dy;
        if (Y < 0 || Y >= HO) continue;
        int w = bil_w8(Y, r);
        if (w == 0) continue;
        int lbl = masks[(b * HO + Y) * HO + X];
        if ((unsigned)lbl < (unsigned)K) {
            uint64_t add = (uint64_t)w << ((lbl & 7) * 8);
            int sel = lbl >> 3;
            if (sel == 0)      a0 += add;
            else if (sel == 1) a1 += add;
            else               a2 += add;
        }
    }
    uint64_t* Tp = &g_T[(((size_t)b * HIN + r) * HO + X) * 3];
    Tp[0] = a0; Tp[1] = a1; Tp[2] = a2;
}

// ---------------- Kernel B: col-downsample T -> W (float) + integer counts ----
// grid 128, block 256 ; thread -> (b, y, x)
__global__ void kernB() {
    int g = blockIdx.x * blockDim.x + threadIdx.x;   // 0 .. 32767
    int b = g >> 12;
    int y = (g >> 6) & 63;
    int x = g & 63;
    int lane = threadIdx.x & 31;

    unsigned acc[K];
    #pragma unroll
    for (int k = 0; k < K; k++) acc[k] = 0u;

    #pragma unroll
    for (int dx = 0; dx < 8; dx++) {
        int X = 4 * x - 2 + dx;
        if (X < 0 || X >= HO) continue;
        int w = bil_w8(X, x);
        if (w == 0) continue;
        const uint64_t* Tp = &g_T[(((size_t)b * HIN + y) * HO + X) * 3];
        uint64_t a0 = Tp[0], a1 = Tp[1], a2 = Tp[2];
        #pragma unroll
        for (int j = 0; j < 8; j++) acc[j]      += (unsigned)w * (unsigned)((a0 >> (8 * j)) & 0xFFull);
        #pragma unroll
        for (int j = 0; j < 8; j++) acc[8 + j]  += (unsigned)w * (unsigned)((a1 >> (8 * j)) & 0xFFull);
        #pragma unroll
        for (int j = 0; j < 5; j++) acc[16 + j] += (unsigned)w * (unsigned)((a2 >> (8 * j)) & 0xFFull);
    }
    int s = y * HIN + x;
    float* Wb = &g_W[(size_t)b * K * S];
    #pragma unroll
    for (int k = 0; k < K; k++)
        Wb[k * S + s] = (float)acc[k] * (1.0f / 64.0f);

    // exact integer counts: warp-reduce then one atomic per (warp, k).
    // all threads in a warp share the same b (4096 threads per b).
    #pragma unroll
    for (int k = 0; k < K; k++) {
        unsigned v = acc[k];
        #pragma unroll
        for (int o = 16; o > 0; o >>= 1) v += __shfl_xor_sync(0xFFFFFFFFu, v, o);
        if (lane == 0 && v) atomicAdd(&g_icounts[b * K + k], v);
    }
}

// ---------------- Kernel D: sums[sp,b,k,c] = sum_{s in range} feats*W ---------
// grid (C/32, B, SPLIT), block 256 = 8 warps; each warp owns 4 channels.
// Channel pairs packed into f32x2; W broadcast into both halves via MOV packs.
__global__ __launch_bounds__(256, 1) void kernD(const float* __restrict__ feats) {
    int b     = blockIdx.y;
    int split = blockIdx.z;
    int warp  = threadIdx.x >> 5;
    int lane  = threadIdx.x & 31;
    int c0    = blockIdx.x * 32 + warp * 4;

    __shared__ float4 Ws4[K * (SCH / 4)];   // 21*128 float4 = 43008 B

    uint64_t acc01[K], acc23[K];
    #pragma unroll
    for (int k = 0; k < K; k++) { acc01[k] = 0ull; acc23[k] = 0ull; }

    const float4* f4 = (const float4*)(feats + ((size_t)b * C + c0) * S);
    const float4* Wg = (const float4*)(&g_W[(size_t)b * K * S]);

    const int s4start = split * (S / SPLIT / 4);          // 256 float4 per split
    #pragma unroll 1
    for (int chunk = 0; chunk < (S / SPLIT) / SCH; chunk++) {
        int s4base = s4start + chunk * (SCH / 4);
        __syncthreads();
        for (int i = threadIdx.x; i < K * (SCH / 4); i += 256) {
            int k = i >> 7;
            int j = i & 127;
            Ws4[i] = Wg[k * (S / 4) + s4base + j];
        }
        __syncthreads();
        #pragma unroll
        for (int i = 0; i < (SCH / 4) / 32; i++) {
            int sl = i * 32 + lane;
            float4 f0 = f4[0 * (S / 4) + s4base + sl];
            float4 f1 = f4[1 * (S / 4) + s4base + sl];
            float4 f2 = f4[2 * (S / 4) + s4base + sl];
            float4 f3 = f4[3 * (S / 4) + s4base + sl];
            uint64_t p01x = pack2(f0.x, f1.x), p23x = pack2(f2.x, f3.x);
            uint64_t p01y = pack2(f0.y, f1.y), p23y = pack2(f2.y, f3.y);
            uint64_t p01z = pack2(f0.z, f1.z), p23z = pack2(f2.z, f3.z);
            uint64_t p01w = pack2(f0.w, f1.w), p23w = pack2(f2.w, f3.w);
            #pragma unroll
            for (int k = 0; k < K; k++) {
                float4 w = Ws4[k * (SCH / 4) + sl];
                uint64_t wx = pack2(w.x, w.x);
                uint64_t wy = pack2(w.y, w.y);
                uint64_t wz = pack2(w.z, w.z);
                uint64_t ww = pack2(w.w, w.w);
                fma2(acc01[k], p01x, wx); fma2(acc23[k], p23x, wx);
                fma2(acc01[k], p01y, wy); fma2(acc23[k], p23y, wy);
                fma2(acc01[k], p01z, wz); fma2(acc23[k], p23z, wz);
                fma2(acc01[k], p01w, ww); fma2(acc23[k], p23w, ww);
            }
        }
    }

    // unpack, warp-reduce each of the 4 channels per class, store partials
    float* outp = &g_sums[(((size_t)split * B + b) * K) * C];
    #pragma unroll
    for (int k = 0; k < K; k++) {
        float v0, v1, v2, v3;
        unpack2(v0, v1, acc01[k]);
        unpack2(v2, v3, acc23[k]);
        #pragma unroll
        for (int o = 16; o > 0; o >>= 1) {
            v0 += __shfl_xor_sync(0xFFFFFFFFu, v0, o);
            v1 += __shfl_xor_sync(0xFFFFFFFFu, v1, o);
            v2 += __shfl_xor_sync(0xFFFFFFFFu, v2, o);
            v3 += __shfl_xor_sync(0xFFFFFFFFu, v3, o);
        }
        if (lane == 0) {
            outp[k * C + c0 + 0] = v0;
            outp[k * C + c0 + 1] = v1;
            outp[k * C + c0 + 2] = v2;
            outp[k * C + c0 + 3] = v3;
        }
    }
}

// ---------------- Kernel E: finalize prototypes ------------------------------
// grid K, block 256
__global__ void kernE(float* __restrict__ out) {
    int k = blockIdx.x;
    int c = threadIdx.x;
    __shared__ float inv[B];
    if (c < B)
        inv[c] = 1.0f / ((float)g_icounts[c * K + k] * (1.0f / 64.0f) + EPSF);
    __syncthreads();
    float v = 0.f;
    #pragma unroll
    for (int b = 0; b < B; b++) {
        float sb = 0.f;
        #pragma unroll
        for (int sp = 0; sp < SPLIT; sp++)
            sb += g_sums[(((size_t)sp * B + b) * K + k) * C + c];
        v += sb * inv[b];
    }
    out[k * C + c] = v * (1.0f / (float)B);
}

// ---------------- launch -----------------------------------------------------
extern "C" void kernel_launch(void* const* d_in, const int* in_sizes, int n_in,
                              void* d_out, int out_size) {
    const float* feats = (const float*)d_in[0];   // [8,256,64,64]
    const int*   masks = (const int*)d_in[1];     // [8,256,256]
    float*       out   = (float*)d_out;           // [21,256]

    kernA<<<dim3(HIN, B), 256>>>(masks);
    kernB<<<128, 256>>>();
    kernD<<<dim3(C / 32, B, SPLIT), 256>>>(feats);
    kernE<<<K, 256>>>(out);
}

// round 5
// speedup vs baseline: 1.2393x; 1.0429x over previous
#include <cuda_runtime.h>
#include <stdint.h>

// Shapes (fixed by the problem)
#define B    8
#define C    256
#define HIN  64          // input spatial 64x64
#define S    (HIN*HIN)   // 4096
#define HO   256         // output spatial 256x256
#define K    21
#define EPSF 1e-6f

#define SPLIT  32        // s-range splits for kernD parallelism (grid = 32x8 = 256 CTAs)
#define SRANGE (S/SPLIT) // 128 s per block
#define SCH    64        // s per smem chunk
#define FSTR   65        // padded row stride (floats) for feats smem tile

#define SMEM_D (K*SCH*8 + C*FSTR*4)   // 10752 + 66560 = 77312 B

// ---------------- scratch (__device__ globals; no allocations) ----------------
__device__ uint64_t g_T[B * HIN * HO * 3];        // [b][r][X] x3 u64 (8-bit class fields, 1/8 units)
__device__ float    g_W[B * K * S];               // [b][k][s] weights (multiples of 1/64)
__device__ unsigned g_icounts[B * K];             // 64 * pixel count (exact integer)
__device__ float    g_sums[SPLIT * B * K * C];    // partial per-image per-class feature sums

// bilinear gather weight (in 1/8 units) of input index r from output index Yx
__device__ __forceinline__ int bil_w8(int Yx, int r) {
    int t  = 2 * Yx - 3;            // 8*iy
    int y0 = ((t + 8) >> 3) - 1;    // floor(iy)
    int f8 = (t + 8) & 7;           // 8*frac
    int y0c = min(max(y0, 0), HIN - 1);
    int y1c = min(max(y0 + 1, 0), HIN - 1);
    int w = 0;
    if (y0c == r) w += 8 - f8;
    if (y1c == r) w += f8;
    return w;
}

// packed f32x2 helpers (sm_103a FFMA2 — ptxas will not auto-fuse from C++)
__device__ __forceinline__ void fma2(uint64_t& d, uint64_t a, uint64_t b) {
    asm("fma.rn.f32x2 %0, %1, %2, %0;" : "+l"(d) : "l"(a), "l"(b));
}
__device__ __forceinline__ uint64_t pack2(float x, float y) {
    uint64_t r; asm("mov.b64 %0, {%1, %2};" : "=l"(r) : "f"(x), "f"(y)); return r;
}
__device__ __forceinline__ void unpack2(float& x, float& y, uint64_t a) {
    asm("mov.b64 {%0, %1}, %2;" : "=f"(x), "=f"(y) : "l"(a));
}

// ---------------- Kernel A: row-downsample one-hot masks (integer, packed) ----
// grid (HIN, B), block 256 (threads = output column X); also zeroes g_icounts
__global__ void kernA(const int* __restrict__ masks) {
    int r = blockIdx.x;
    int b = blockIdx.y;
    int X = threadIdx.x;
    if (r == 0 && b == 0 && X < B * K) g_icounts[X] = 0u;

    uint64_t a0 = 0, a1 = 0, a2 = 0;
    #pragma unroll
    for (int dy = 0; dy < 8; dy++) {
        int Y = 4 * r - 2 + dy;
        if (Y < 0 || Y >= HO) continue;
        int w = bil_w8(Y, r);
        if (w == 0) continue;
        int lbl = masks[(b * HO + Y) * HO + X];
        if ((unsigned)lbl < (unsigned)K) {
            uint64_t add = (uint64_t)w << ((lbl & 7) * 8);
            int sel = lbl >> 3;
            if (sel == 0)      a0 += add;
            else if (sel == 1) a1 += add;
            else               a2 += add;
        }
    }
    uint64_t* Tp = &g_T[(((size_t)b * HIN + r) * HO + X) * 3];
    Tp[0] = a0; Tp[1] = a1; Tp[2] = a2;
}

// ---------------- Kernel B: col-downsample T -> W (float) + integer counts ----
// grid 128, block 256 ; thread -> (b, y, x)
__global__ void kernB() {
    int g = blockIdx.x * blockDim.x + threadIdx.x;   // 0 .. 32767
    int b = g >> 12;
    int y = (g >> 6) & 63;
    int x = g & 63;
    int lane = threadIdx.x & 31;

    unsigned acc[K];
    #pragma unroll
    for (int k = 0; k < K; k++) acc[k] = 0u;

    #pragma unroll
    for (int dx = 0; dx < 8; dx++) {
        int X = 4 * x - 2 + dx;
        if (X < 0 || X >= HO) continue;
        int w = bil_w8(X, x);
        if (w == 0) continue;
        const uint64_t* Tp = &g_T[(((size_t)b * HIN + y) * HO + X) * 3];
        uint64_t a0 = Tp[0], a1 = Tp[1], a2 = Tp[2];
        #pragma unroll
        for (int j = 0; j < 8; j++) acc[j]      += (unsigned)w * (unsigned)((a0 >> (8 * j)) & 0xFFull);
        #pragma unroll
        for (int j = 0; j < 8; j++) acc[8 + j]  += (unsigned)w * (unsigned)((a1 >> (8 * j)) & 0xFFull);
        #pragma unroll
        for (int j = 0; j < 5; j++) acc[16 + j] += (unsigned)w * (unsigned)((a2 >> (8 * j)) & 0xFFull);
    }
    int s = y * HIN + x;
    float* Wb = &g_W[(size_t)b * K * S];
    #pragma unroll
    for (int k = 0; k < K; k++)
        Wb[k * S + s] = (float)acc[k] * (1.0f / 64.0f);

    // exact integer counts: warp-reduce then one atomic per (warp, k)
    #pragma unroll
    for (int k = 0; k < K; k++) {
        unsigned v = acc[k];
        #pragma unroll
        for (int o = 16; o > 0; o >>= 1) v += __shfl_xor_sync(0xFFFFFFFFu, v, o);
        if (lane == 0 && v) atomicAdd(&g_icounts[b * K + k], v);
    }
}

// ---------------- Kernel D: sums[sp,b,k,c] = sum_{s in range} feats*W ---------
// grid (SPLIT, B), block 256 = 8 warps = 4 channel-groups x 2 s-subranges.
// lane = channel-pair (c, c+128): W[k,s] is a warp-uniform smem BROADCAST
// (pre-duplicated f32x2 at load time) -> 64-way channel reuse per LDS,
// and fully packed fma.rn.f32x2 with zero per-iteration w packing.
extern "C" __global__ void __launch_bounds__(256, 2) kernD(const float* __restrict__ feats) {
    extern __shared__ unsigned char smem[];
    uint64_t* Wd = (uint64_t*)smem;                 // [K][SCH] dup pairs (w,w)
    float*    Fs = (float*)(smem + K * SCH * 8);    // [C][FSTR] transposed-free padded tile

    int split = blockIdx.x, b = blockIdx.y;
    int tid = threadIdx.x, warp = tid >> 5, lane = tid & 31;
    int g = warp & 3, sub = warp >> 2;
    int sbase0 = split * SRANGE;

    uint64_t acc[K];
    #pragma unroll
    for (int k = 0; k < K; k++) acc[k] = 0ull;

    const float* Wg = &g_W[(size_t)b * K * S];
    const float* Fg = feats + (size_t)b * C * S;

    #pragma unroll 1
    for (int chunk = 0; chunk < SRANGE / SCH; chunk++) {
        int sbase = sbase0 + chunk * SCH;
        __syncthreads();
        // stage W chunk, duplicated into f32x2 pairs
        for (int i = tid; i < K * SCH; i += 256) {
            int k = i >> 6, j = i & 63;
            float w = Wg[k * S + sbase + j];
            Wd[i] = pack2(w, w);
        }
        // stage feats chunk: 256 c x 64 s (coalesced float4 reads, <=2-way STS)
        for (int i4 = tid; i4 < C * SCH / 4; i4 += 256) {
            int c = i4 >> 4, j4 = i4 & 15;
            float4 v = *(const float4*)&Fg[(size_t)c * S + sbase + j4 * 4];
            float* dst = &Fs[c * FSTR + j4 * 4];
            dst[0] = v.x; dst[1] = v.y; dst[2] = v.z; dst[3] = v.w;
        }
        __syncthreads();

        const float* fA = &Fs[(g * 32 + lane) * FSTR];          // channel c
        const float* fB = &Fs[(g * 32 + lane + 128) * FSTR];    // channel c+128
        int sb = sub * 32;
        #pragma unroll 2
        for (int i = 0; i < 32; i += 4) {
            int s = sb + i;
            uint64_t p0 = pack2(fA[s + 0], fB[s + 0]);
            uint64_t p1 = pack2(fA[s + 1], fB[s + 1]);
            uint64_t p2 = pack2(fA[s + 2], fB[s + 2]);
            uint64_t p3 = pack2(fA[s + 3], fB[s + 3]);
            #pragma unroll
            for (int k = 0; k < K; k++) {
                ulonglong2 w01 = *(const ulonglong2*)&Wd[k * SCH + s];       // broadcast
                ulonglong2 w23 = *(const ulonglong2*)&Wd[k * SCH + s + 2];   // broadcast
                fma2(acc[k], p0, w01.x);
                fma2(acc[k], p1, w01.y);
                fma2(acc[k], p2, w23.x);
                fma2(acc[k], p3, w23.y);
            }
        }
    }

    // combine the two s-subrange warps per channel-group via smem, then store
    __syncthreads();
    uint64_t* red = (uint64_t*)smem;   // 4 groups x K x 32 lanes u64 = 21 KB (fits)
    if (sub == 1) {
        #pragma unroll
        for (int k = 0; k < K; k++) red[(g * K + k) * 32 + lane] = acc[k];
    }
    __syncthreads();
    if (sub == 0) {
        float* outp = &g_sums[(((size_t)split * B + b) * K) * C];
        #pragma unroll
        for (int k = 0; k < K; k++) {
            float ax, ay, ox, oy;
            unpack2(ax, ay, acc[k]);
            unpack2(ox, oy, red[(g * K + k) * 32 + lane]);
            outp[k * C + g * 32 + lane]       = ax + ox;
            outp[k * C + g * 32 + lane + 128] = ay + oy;
        }
    }
}

// ---------------- Kernel E: finalize prototypes ------------------------------
// grid (K, 4), block 256: 64 channels per block, 4-way (b) thread split
__global__ void kernE(float* __restrict__ out) {
    int k = blockIdx.x, cg = blockIdx.y;
    int tid = threadIdx.x;
    int cl = tid & 63, r = tid >> 6;
    int c = cg * 64 + cl;

    float v = 0.f;
    #pragma unroll
    for (int bb = 0; bb < 2; bb++) {
        int b = r + bb * 4;
        float sb = 0.f;
        #pragma unroll
        for (int sp = 0; sp < SPLIT; sp++)
            sb += g_sums[(((size_t)sp * B + b) * K + k) * C + c];
        float cnt = (float)g_icounts[b * K + k] * (1.0f / 64.0f) + EPSF;
        v += sb / cnt;
    }
    __shared__ float red[256];
    red[tid] = v;
    __syncthreads();
    if (r == 0) {
        float t = red[cl] + red[cl + 64] + red[cl + 128] + red[cl + 192];
        out[k * C + c] = t * (1.0f / (float)B);
    }
}

// ---------------- launch -----------------------------------------------------
extern "C" void kernel_launch(void* const* d_in, const int* in_sizes, int n_in,
                              void* d_out, int out_size) {
    const float* feats = (const float*)d_in[0];   // [8,256,64,64]
    const int*   masks = (const int*)d_in[1];     // [8,256,256]
    float*       out   = (float*)d_out;           // [21,256]

    cudaFuncSetAttribute(kernD, cudaFuncAttributeMaxDynamicSharedMemorySize, SMEM_D);

    kernA<<<dim3(HIN, B), 256>>>(masks);
    kernB<<<128, 256>>>();
    kernD<<<dim3(SPLIT, B), 256, SMEM_D>>>(feats);
    kernE<<<dim3(K, 4), 256>>>(out);
}

// round 6
// speedup vs baseline: 1.4826x; 1.1963x over previous
#include <cuda_runtime.h>
#include <stdint.h>

// Shapes (fixed by the problem)
#define B    8
#define C    256
#define HIN  64          // input spatial 64x64
#define S    (HIN*HIN)   // 4096
#define HO   256         // output spatial 256x256
#define K    21
#define EPSF 1e-6f

#define SPLIT  16        // s-range splits for kernD parallelism (grid = 16x8 = 128 CTAs)
#define SRANGE (S/SPLIT) // 256 s per block
#define SCH    64        // s per smem chunk
#define FSTR   65        // padded row stride (floats) for feats smem tile

#define SMEM_D (K*SCH*8 + C*FSTR*4)   // 10752 + 66560 = 77312 B

// ---------------- scratch (__device__ globals; no allocations) ----------------
__device__ float    g_W[B * K * S];               // [b][k][s] weights (multiples of 1/64)
__device__ unsigned g_rowcnt[B * K * HIN];        // exact 64*count per (b,k,y) row
__device__ float    g_sums[SPLIT * B * K * C];    // partial per-image per-class feature sums

// bilinear gather weight (in 1/8 units) of input index r from output index Yx
__device__ __forceinline__ int bil_w8(int Yx, int r) {
    int t  = 2 * Yx - 3;            // 8*iy
    int y0 = ((t + 8) >> 3) - 1;    // floor(iy)
    int f8 = (t + 8) & 7;           // 8*frac
    int y0c = min(max(y0, 0), HIN - 1);
    int y1c = min(max(y0 + 1, 0), HIN - 1);
    int w = 0;
    if (y0c == r) w += 8 - f8;
    if (y1c == r) w += f8;
    return w;
}

// packed f32x2 helpers (sm_103a FFMA2 — ptxas will not auto-fuse from C++)
__device__ __forceinline__ void fma2(uint64_t& d, uint64_t a, uint64_t b) {
    asm("fma.rn.f32x2 %0, %1, %2, %0;" : "+l"(d) : "l"(a), "l"(b));
}
__device__ __forceinline__ uint64_t add2(uint64_t a, uint64_t b) {
    uint64_t d; asm("add.rn.f32x2 %0, %1, %2;" : "=l"(d) : "l"(a), "l"(b)); return d;
}
__device__ __forceinline__ uint64_t pack2(float x, float y) {
    uint64_t r; asm("mov.b64 %0, {%1, %2};" : "=l"(r) : "f"(x), "f"(y)); return r;
}
__device__ __forceinline__ void unpack2(float& x, float& y, uint64_t a) {
    asm("mov.b64 {%0, %1}, %2;" : "=f"(x), "=f"(y) : "l"(a));
}

// ---------------- Kernel AB: masks -> W + exact row counts (fused, no gmem T) -
// grid (HIN, B), block 256. Phase 1: 256 threads build row-downsampled one-hot
// T[X] in smem (3x u64, 8-bit class fields, 1/8 units). Phase 2: 256 threads =
// 64 x * 4 class-quarters column-downsample T -> W[b,:,y,:] and row counts.
__global__ void kernAB(const int* __restrict__ masks) {
    __shared__ uint64_t Ts[HO * 3];            // 6144 B
    __shared__ unsigned Cs[K][HIN + 1];        // padded vs bank conflicts

    int y = blockIdx.x, b = blockIdx.y;
    int tid = threadIdx.x;

    // phase 1: X = tid
    {
        uint64_t a0 = 0, a1 = 0, a2 = 0;
        #pragma unroll
        for (int dy = 0; dy < 8; dy++) {
            int Y = 4 * y - 2 + dy;
            if (Y < 0 || Y >= HO) continue;
            int w = bil_w8(Y, y);
            if (w == 0) continue;
            int lbl = masks[(b * HO + Y) * HO + tid];
            if ((unsigned)lbl < (unsigned)K) {
                uint64_t add = (uint64_t)w << ((lbl & 7) * 8);
                int sel = lbl >> 3;
                if (sel == 0)      a0 += add;
                else if (sel == 1) a1 += add;
                else               a2 += add;
            }
        }
        Ts[tid * 3 + 0] = a0; Ts[tid * 3 + 1] = a1; Ts[tid * 3 + 2] = a2;
    }
    __syncthreads();

    // phase 2: (x, class-quarter)
    int x = tid & 63, kq = tid >> 6;
    int kbase = kq * 6;
    int kcnt  = (kq == 3) ? 3 : 6;
    unsigned acc[6] = {0, 0, 0, 0, 0, 0};
    #pragma unroll
    for (int dx = 0; dx < 8; dx++) {
        int X = 4 * x - 2 + dx;
        if (X < 0 || X >= HO) continue;
        int w = bil_w8(X, x);
        if (w == 0) continue;
        const uint64_t* Tp = &Ts[X * 3];
        uint64_t t0 = Tp[0], t1 = Tp[1], t2 = Tp[2];
        #pragma unroll
        for (int j = 0; j < 6; j++) {
            if (j < kcnt) {
                int k = kbase + j;
                uint64_t word = (k < 8) ? t0 : ((k < 16) ? t1 : t2);
                unsigned byte = (unsigned)((word >> ((k & 7) * 8)) & 0xFFull);
                acc[j] += (unsigned)w * byte;
            }
        }
    }
    int s = y * HIN + x;
    float* Wb = &g_W[(size_t)b * K * S];
    #pragma unroll
    for (int j = 0; j < 6; j++) {
        if (j < kcnt) {
            Wb[(kbase + j) * S + s] = (float)acc[j] * (1.0f / 64.0f);
            Cs[kbase + j][x] = acc[j];
        }
    }
    __syncthreads();
    // exact integer row counts (no atomics; deterministic)
    if (tid < K) {
        unsigned t = 0;
        #pragma unroll 8
        for (int xx = 0; xx < HIN; xx++) t += Cs[tid][xx];
        g_rowcnt[(b * K + tid) * HIN + y] = t;
    }
}

// ---------------- Kernel D: sums[sp,b,k,c] = sum_{s in range} feats*W ---------
// grid (SPLIT, B), block 512 = 16 warps = 4 channel-groups x 4 s-subranges.
// lane = channel-pair (c, c+128): W[k,s] is a warp-uniform smem BROADCAST
// (pre-duplicated f32x2 at load time) -> 64-way channel reuse per LDS,
// fully packed fma.rn.f32x2, zero per-iteration w packing.
extern "C" __global__ void __launch_bounds__(512, 1) kernD(const float* __restrict__ feats) {
    extern __shared__ unsigned char smem[];
    uint64_t* Wd = (uint64_t*)smem;                 // [K][SCH] dup pairs (w,w)
    float*    Fs = (float*)(smem + K * SCH * 8);    // [C][FSTR] padded tile

    int split = blockIdx.x, b = blockIdx.y;
    int tid = threadIdx.x, warp = tid >> 5, lane = tid & 31;
    int g = warp & 3, sub = warp >> 2;              // 4 cgroups x 4 subranges
    int sbase0 = split * SRANGE;

    uint64_t acc[K];
    #pragma unroll
    for (int k = 0; k < K; k++) acc[k] = 0ull;

    const float* Wg = &g_W[(size_t)b * K * S];
    const float* Fg = feats + (size_t)b * C * S;

    #pragma unroll 1
    for (int chunk = 0; chunk < SRANGE / SCH; chunk++) {
        int sbase = sbase0 + chunk * SCH;
        __syncthreads();
        // stage W chunk, duplicated into f32x2 pairs
        for (int i = tid; i < K * SCH; i += 512) {
            int k = i >> 6, j = i & 63;
            float w = Wg[k * S + sbase + j];
            Wd[i] = pack2(w, w);
        }
        // stage feats chunk: 256 c x 64 s (coalesced float4 reads)
        for (int i4 = tid; i4 < C * SCH / 4; i4 += 512) {
            int c = i4 >> 4, j4 = i4 & 15;
            float4 v = *(const float4*)&Fg[(size_t)c * S + sbase + j4 * 4];
            float* dst = &Fs[c * FSTR + j4 * 4];
            dst[0] = v.x; dst[1] = v.y; dst[2] = v.z; dst[3] = v.w;
        }
        __syncthreads();

        const float* fA = &Fs[(g * 32 + lane) * FSTR];          // channel c
        const float* fB = &Fs[(g * 32 + lane + 128) * FSTR];    // channel c+128
        int sb = sub * 16;
        #pragma unroll 2
        for (int i = 0; i < 16; i += 4) {
            int s = sb + i;
            uint64_t p0 = pack2(fA[s + 0], fB[s + 0]);
            uint64_t p1 = pack2(fA[s + 1], fB[s + 1]);
            uint64_t p2 = pack2(fA[s + 2], fB[s + 2]);
            uint64_t p3 = pack2(fA[s + 3], fB[s + 3]);
            #pragma unroll
            for (int k = 0; k < K; k++) {
                ulonglong2 w01 = *(const ulonglong2*)&Wd[k * SCH + s];       // broadcast
                ulonglong2 w23 = *(const ulonglong2*)&Wd[k * SCH + s + 2];   // broadcast
                fma2(acc[k], p0, w01.x);
                fma2(acc[k], p1, w01.y);
                fma2(acc[k], p2, w23.x);
                fma2(acc[k], p3, w23.y);
            }
        }
    }

    // reduce the 4 s-subrange warps per channel-group via smem (two steps)
    __syncthreads();
    uint64_t* red = (uint64_t*)smem;   // step1: 4g x 2 x K x 32 u64 = 43008 B (fits)
    if (sub >= 2) {
        #pragma unroll
        for (int k = 0; k < K; k++) red[((g * 2 + (sub - 2)) * K + k) * 32 + lane] = acc[k];
    }
    __syncthreads();
    if (sub < 2) {
        #pragma unroll
        for (int k = 0; k < K; k++) acc[k] = add2(acc[k], red[((g * 2 + sub) * K + k) * 32 + lane]);
    }
    __syncthreads();
    if (sub == 1) {
        #pragma unroll
        for (int k = 0; k < K; k++) red[(g * K + k) * 32 + lane] = acc[k];
    }
    __syncthreads();
    if (sub == 0) {
        float* outp = &g_sums[(((size_t)split * B + b) * K) * C];
        #pragma unroll
        for (int k = 0; k < K; k++) {
            uint64_t t = add2(acc[k], red[(g * K + k) * 32 + lane]);
            float ax, ay;
            unpack2(ax, ay, t);
            outp[k * C + g * 32 + lane]       = ax;
            outp[k * C + g * 32 + lane + 128] = ay;
        }
    }
}

// ---------------- Kernel E: finalize prototypes ------------------------------
// grid (K, 2), block 256 = 8 warps (one per b) x 32 lanes (float4 of channels).
// 16 independent float4 loads per thread; exact counts from rowcnt, no atomics.
__global__ void kernE(float* __restrict__ out) {
    int k = blockIdx.x, cg = blockIdx.y;
    int tid = threadIdx.x, b = tid >> 5, lane = tid & 31;
    int c4 = cg * 32 + lane;

    const float4* Sp = (const float4*)g_sums;
    float4 v = make_float4(0.f, 0.f, 0.f, 0.f);
    #pragma unroll
    for (int sp = 0; sp < SPLIT; sp++) {
        float4 t = Sp[((sp * B + b) * K + k) * (C / 4) + c4];
        v.x += t.x; v.y += t.y; v.z += t.z; v.w += t.w;
    }
    // exact count for (b,k): warp-reduce 64 row counts
    const unsigned* rc = &g_rowcnt[(b * K + k) * HIN];
    unsigned cr = rc[lane] + rc[lane + 32];
    #pragma unroll
    for (int o = 16; o > 0; o >>= 1) cr += __shfl_xor_sync(0xFFFFFFFFu, cr, o);
    float inv = 1.0f / ((float)cr * (1.0f / 64.0f) + EPSF);
    v.x *= inv; v.y *= inv; v.z *= inv; v.w *= inv;

    __shared__ float4 red[B][32];
    red[b][lane] = v;
    __syncthreads();
    if (b == 0) {
        float4 a = red[0][lane];
        #pragma unroll
        for (int w = 1; w < B; w++) {
            float4 t = red[w][lane];
            a.x += t.x; a.y += t.y; a.z += t.z; a.w += t.w;
        }
        float sc = 1.0f / (float)B;
        a.x *= sc; a.y *= sc; a.z *= sc; a.w *= sc;
        ((float4*)out)[k * (C / 4) + c4] = a;
    }
}

// ---------------- launch -----------------------------------------------------
extern "C" void kernel_launch(void* const* d_in, const int* in_sizes, int n_in,
                              void* d_out, int out_size) {
    const float* feats = (const float*)d_in[0];   // [8,256,64,64]
    const int*   masks = (const int*)d_in[1];     // [8,256,256]
    float*       out   = (float*)d_out;           // [21,256]

    cudaFuncSetAttribute(kernD, cudaFuncAttributeMaxDynamicSharedMemorySize, SMEM_D);

    kernAB<<<dim3(HIN, B), 256>>>(masks);
    kernD<<<dim3(SPLIT, B), 512, SMEM_D>>>(feats);
    kernE<<<dim3(K, 2), 256>>>(out);
}

// round 7
// speedup vs baseline: 1.5435x; 1.0411x over previous
#include <cuda_runtime.h>
#include <stdint.h>

// Shapes (fixed by the problem)
#define B    8
#define C    256
#define HIN  64          // input spatial 64x64
#define S    (HIN*HIN)   // 4096
#define HO   256         // output spatial 256x256
#define K    21
#define EPSF 1e-6f

#define SPLIT  16        // s-range splits for kernD (grid = 16x8 = 128 CTAs)
#define SRANGE (S/SPLIT) // 256 s per block
#define SCH    64        // s per smem chunk
#define NCH    (SRANGE/SCH)
#define FSTR   68        // padded row stride (floats): 272B = 16x17, conflict-free float4
#define SMEM_D (2*K*SCH*8 + 2*C*FSTR*4)   // 21504 + 139264 = 160768 B

// ---------------- scratch (__device__ globals; no allocations) ----------------
__device__ uint64_t g_W2[B * K * S];              // [b][k][s] duplicated (w,w) f32x2 pairs
__device__ unsigned g_rowcnt[B * K * HIN];        // exact 64*count per (b,k,y) row
__device__ float    g_sums[SPLIT * B * K * C];    // partial per-image per-class sums

// bilinear gather weight (in 1/8 units) of input index r from output index Yx
__device__ __forceinline__ int bil_w8(int Yx, int r) {
    int t  = 2 * Yx - 3;
    int y0 = ((t + 8) >> 3) - 1;
    int f8 = (t + 8) & 7;
    int y0c = min(max(y0, 0), HIN - 1);
    int y1c = min(max(y0 + 1, 0), HIN - 1);
    int w = 0;
    if (y0c == r) w += 8 - f8;
    if (y1c == r) w += f8;
    return w;
}

// packed f32x2 helpers (sm_103a FFMA2 — ptxas will not auto-fuse from C++)
__device__ __forceinline__ void fma2(uint64_t& d, uint64_t a, uint64_t b) {
    asm("fma.rn.f32x2 %0, %1, %2, %0;" : "+l"(d) : "l"(a), "l"(b));
}
__device__ __forceinline__ uint64_t add2(uint64_t a, uint64_t b) {
    uint64_t d; asm("add.rn.f32x2 %0, %1, %2;" : "=l"(d) : "l"(a), "l"(b)); return d;
}
__device__ __forceinline__ uint64_t pack2(float x, float y) {
    uint64_t r; asm("mov.b64 %0, {%1, %2};" : "=l"(r) : "f"(x), "f"(y)); return r;
}
__device__ __forceinline__ void unpack2(float& x, float& y, uint64_t a) {
    asm("mov.b64 {%0, %1}, %2;" : "=f"(x), "=f"(y) : "l"(a));
}
// expand 4 bytes -> 4x 16-bit lanes of a u64
__device__ __forceinline__ uint64_t exp16(unsigned v) {
    return (uint64_t)(v & 0xFFu) | ((uint64_t)(v & 0xFF00u) << 8)
         | ((uint64_t)(v & 0xFF0000u) << 16) | ((uint64_t)(v & 0xFF000000u) << 24);
}
// cp.async 16B
__device__ __forceinline__ void cp16(void* dst, const void* src) {
    unsigned u = (unsigned)__cvta_generic_to_shared(dst);
    asm volatile("cp.async.cg.shared.global [%0], [%1], 16;" :: "r"(u), "l"(src));
}

// ---------------- Kernel AB: masks -> W2 (dup pairs) + exact row counts ------
// grid (HIN, B), block 256.
// Phase 1: X = tid, row-downsample one-hot into 8-bit fields, expand to 16-bit
//          lanes in smem (6 u64 per X: 4 classes x 16-bit each).
// Phase 2: (x, dx-quarter): acc[j] += T16[j]*w — 6 IMAD.WIDE per dx, SIMD in
//          register (max field 1024 < 2^16, no overflow). smem tree over dq.
__global__ void kernAB(const int* __restrict__ masks) {
    __shared__ uint64_t T16[HO * 6];          // 12288 B
    __shared__ uint64_t Rs[256 * 6];          // 12288 B
    __shared__ uint64_t Fin[HIN * 6];         // 3072 B
    __shared__ unsigned Cs[K][HIN + 4];

    int y = blockIdx.x, b = blockIdx.y;
    int tid = threadIdx.x;

    // phase 1: X = tid
    {
        uint64_t a0 = 0, a1 = 0, a2 = 0;
        #pragma unroll
        for (int dy = 0; dy < 8; dy++) {
            int Y = 4 * y - 2 + dy;
            if (Y < 0 || Y >= HO) continue;
            int w = bil_w8(Y, y);
            if (w == 0) continue;
            int lbl = masks[(b * HO + Y) * HO + tid];
            if ((unsigned)lbl < (unsigned)K) {
                uint64_t add = (uint64_t)w << ((lbl & 7) * 8);
                int sel = lbl >> 3;
                if (sel == 0)      a0 += add;
                else if (sel == 1) a1 += add;
                else               a2 += add;
            }
        }
        uint64_t* Tp = &T16[tid * 6];
        Tp[0] = exp16((unsigned)a0); Tp[1] = exp16((unsigned)(a0 >> 32));
        Tp[2] = exp16((unsigned)a1); Tp[3] = exp16((unsigned)(a1 >> 32));
        Tp[4] = exp16((unsigned)a2); Tp[5] = exp16((unsigned)(a2 >> 32));
    }
    __syncthreads();

    // phase 2: x = tid&63, dq = tid>>6 handles dx in {2dq, 2dq+1}
    {
        int x = tid & 63, dq = tid >> 6;
        uint64_t acc[6] = {0, 0, 0, 0, 0, 0};
        #pragma unroll
        for (int t = 0; t < 2; t++) {
            int dx = dq * 2 + t;
            int X = 4 * x - 2 + dx;
            if (X < 0 || X >= HO) continue;
            unsigned w = (unsigned)bil_w8(X, x);
            if (w == 0) continue;
            const uint64_t* Tp = &T16[X * 6];
            #pragma unroll
            for (int j = 0; j < 6; j++) acc[j] += Tp[j] * (uint64_t)w;
        }
        uint64_t* Rp = &Rs[tid * 6];
        #pragma unroll
        for (int j = 0; j < 6; j++) Rp[j] = acc[j];
    }
    __syncthreads();
    if (tid < 64) {
        #pragma unroll
        for (int j = 0; j < 6; j++)
            Fin[tid * 6 + j] = Rs[tid * 6 + j] + Rs[(64 + tid) * 6 + j]
                             + Rs[(128 + tid) * 6 + j] + Rs[(192 + tid) * 6 + j];
    }
    __syncthreads();

    // spread store: W2 duplicated pairs + Cs for counts
    int srow = y * HIN;
    for (int i = tid; i < K * HIN; i += 256) {
        int k = i >> 6, x2 = i & 63;
        unsigned val = (unsigned)((Fin[x2 * 6 + (k >> 2)] >> ((k & 3) * 16)) & 0xFFFFull);
        float f = (float)val * (1.0f / 64.0f);
        g_W2[((size_t)b * K + k) * S + srow + x2] = pack2(f, f);
        Cs[k][x2] = val;
    }
    __syncthreads();
    if (tid < K) {
        unsigned t = 0;
        #pragma unroll 8
        for (int xx = 0; xx < HIN; xx++) t += Cs[tid][xx];
        g_rowcnt[(b * K + tid) * HIN + y] = t;
    }
}

// ---------------- Kernel D: sums[sp,b,k,c] = sum_{s in range} feats*W ---------
// grid (SPLIT, B), block 512 = 16 warps = 4 channel-groups x 4 s-subranges.
// Double-buffered cp.async staging (feats tile + pre-duplicated W pairs) hides
// all gmem latency; lane = channel-pair (c, c+128); W loads are warp-uniform
// smem broadcasts; fully packed fma.rn.f32x2.
extern "C" __global__ void __launch_bounds__(512, 1) kernD(const float* __restrict__ feats) {
    extern __shared__ unsigned char smem[];
    uint64_t* Wd = (uint64_t*)smem;                       // [2][K*SCH]
    float*    Fs = (float*)(smem + 2 * K * SCH * 8);      // [2][C*FSTR]

    int split = blockIdx.x, b = blockIdx.y;
    int tid = threadIdx.x, warp = tid >> 5, lane = tid & 31;
    int g = warp & 3, sub = warp >> 2;
    int sbase0 = split * SRANGE;

    const float*    Fg  = feats + (size_t)b * C * S;
    const uint64_t* Wg2 = &g_W2[(size_t)b * K * S];

    uint64_t acc[K];
    #pragma unroll
    for (int k = 0; k < K; k++) acc[k] = 0ull;

    // stage helper (inlined twice below)
    #define STAGE(BUF, SB) do {                                                   \
        for (int i = tid; i < C * SCH / 4; i += 512) {                            \
            int c = i >> 4, j4 = i & 15;                                          \
            cp16(&Fs[(BUF) * C * FSTR + c * FSTR + j4 * 4],                       \
                 Fg + (size_t)c * S + (SB) + j4 * 4);                             \
        }                                                                         \
        for (int i = tid; i < K * SCH / 2; i += 512) {                            \
            int k = i >> 5, j2 = i & 31;                                          \
            cp16(&Wd[(BUF) * K * SCH + k * SCH + j2 * 2],                         \
                 Wg2 + (size_t)k * S + (SB) + j2 * 2);                            \
        }                                                                         \
        asm volatile("cp.async.commit_group;");                                   \
    } while (0)

    STAGE(0, sbase0);

    #pragma unroll 1
    for (int chunk = 0; chunk < NCH; chunk++) {
        if (chunk + 1 < NCH) {
            STAGE((chunk + 1) & 1, sbase0 + (chunk + 1) * SCH);
            asm volatile("cp.async.wait_group 1;");
        } else {
            asm volatile("cp.async.wait_group 0;");
        }
        __syncthreads();

        const float* fA = &Fs[(chunk & 1) * C * FSTR + (g * 32 + lane) * FSTR];
        const float* fB = fA + 128 * FSTR;
        const uint64_t* Wb = &Wd[(chunk & 1) * K * SCH];
        int sb = sub * 16;
        #pragma unroll
        for (int i = 0; i < 16; i += 4) {
            int s = sb + i;
            float4 va = *(const float4*)&fA[s];
            float4 vb = *(const float4*)&fB[s];
            uint64_t p0 = pack2(va.x, vb.x);
            uint64_t p1 = pack2(va.y, vb.y);
            uint64_t p2 = pack2(va.z, vb.z);
            uint64_t p3 = pack2(va.w, vb.w);
            #pragma unroll
            for (int k = 0; k < K; k++) {
                ulonglong2 w01 = *(const ulonglong2*)&Wb[k * SCH + s];       // broadcast
                ulonglong2 w23 = *(const ulonglong2*)&Wb[k * SCH + s + 2];   // broadcast
                fma2(acc[k], p0, w01.x);
                fma2(acc[k], p1, w01.y);
                fma2(acc[k], p2, w23.x);
                fma2(acc[k], p3, w23.y);
            }
        }
        __syncthreads();   // protect buffer reuse by next prefetch
    }

    // reduce 4 s-subrange warps per channel-group via smem (two steps)
    uint64_t* red = (uint64_t*)smem;   // 4g x 2 x K x 32 u64 = 43008 B (fits)
    if (sub >= 2) {
        #pragma unroll
        for (int k = 0; k < K; k++) red[((g * 2 + (sub - 2)) * K + k) * 32 + lane] = acc[k];
    }
    __syncthreads();
    if (sub < 2) {
        #pragma unroll
        for (int k = 0; k < K; k++) acc[k] = add2(acc[k], red[((g * 2 + sub) * K + k) * 32 + lane]);
    }
    __syncthreads();
    if (sub == 1) {
        #pragma unroll
        for (int k = 0; k < K; k++) red[(g * K + k) * 32 + lane] = acc[k];
    }
    __syncthreads();
    if (sub == 0) {
        float* outp = &g_sums[(((size_t)split * B + b) * K) * C];
        #pragma unroll
        for (int k = 0; k < K; k++) {
            uint64_t t = add2(acc[k], red[(g * K + k) * 32 + lane]);
            float ax, ay;
            unpack2(ax, ay, t);
            outp[k * C + g * 32 + lane]       = ax;
            outp[k * C + g * 32 + lane + 128] = ay;
        }
    }
}

// ---------------- Kernel E: finalize prototypes ------------------------------
// grid (K, 2), block 256 = 8 warps (one per b) x 32 lanes (float4 of channels)
__global__ void kernE(float* __restrict__ out) {
    int k = blockIdx.x, cg = blockIdx.y;
    int tid = threadIdx.x, b = tid >> 5, lane = tid & 31;
    int c4 = cg * 32 + lane;

    const float4* Sp = (const float4*)g_sums;
    float4 v = make_float4(0.f, 0.f, 0.f, 0.f);
    #pragma unroll
    for (int sp = 0; sp < SPLIT; sp++) {
        float4 t = Sp[((sp * B + b) * K + k) * (C / 4) + c4];
        v.x += t.x; v.y += t.y; v.z += t.z; v.w += t.w;
    }
    const unsigned* rc = &g_rowcnt[(b * K + k) * HIN];
    unsigned cr = rc[lane] + rc[lane + 32];
    #pragma unroll
    for (int o = 16; o > 0; o >>= 1) cr += __shfl_xor_sync(0xFFFFFFFFu, cr, o);
    float inv = 1.0f / ((float)cr * (1.0f / 64.0f) + EPSF);
    v.x *= inv; v.y *= inv; v.z *= inv; v.w *= inv;

    __shared__ float4 red[B][32];
    red[b][lane] = v;
    __syncthreads();
    if (b == 0) {
        float4 a = red[0][lane];
        #pragma unroll
        for (int w = 1; w < B; w++) {
            float4 t = red[w][lane];
            a.x += t.x; a.y += t.y; a.z += t.z; a.w += t.w;
        }
        float sc = 1.0f / (float)B;
        a.x *= sc; a.y *= sc; a.z *= sc; a.w *= sc;
        ((float4*)out)[k * (C / 4) + c4] = a;
    }
}

// ---------------- launch -----------------------------------------------------
extern "C" void kernel_launch(void* const* d_in, const int* in_sizes, int n_in,
                              void* d_out, int out_size) {
    const float* feats = (const float*)d_in[0];   // [8,256,64,64]
    const int*   masks = (const int*)d_in[1];     // [8,256,256]
    float*       out   = (float*)d_out;           // [21,256]

    cudaFuncSetAttribute(kernD, cudaFuncAttributeMaxDynamicSharedMemorySize, SMEM_D);

    kernAB<<<dim3(HIN, B), 256>>>(masks);
    kernD<<<dim3(SPLIT, B), 512, SMEM_D>>>(feats);
    kernE<<<dim3(K, 2), 256>>>(out);
}